// round 3
// baseline (speedup 1.0000x reference)
#include <cuda_runtime.h>
#include <math.h>

#define Bb 8
#define Qn 128
#define Kn 256
#define Dd 512
#define Hh 512
#define Vv 512
#define HUGEF 1000000000.0f

// Scratch (allocation-free rule: __device__ globals)
__device__ float g_qproj[Bb*Qn*Hh];   // 2 MB
__device__ float g_kproj[Bb*Kn*Hh];   // 4 MB (b1 folded in)
__device__ float g_scores[Bb*Qn*Kn];  // 1 MB

__device__ __forceinline__ float fast_tanh(float x){
    float r; asm("tanh.approx.f32 %0, %1;" : "=f"(r) : "f"(x)); return r;
}

// ---------------------------------------------------------------------------
// Kernel 1: projections. Rows 0..1023 = query @ W1[:512]; rows 1024..3071 =
// key @ W1[512:] + b1. 64x64 tile, 256 threads, 4x4 micro-tile, k-chunk 16.
// ---------------------------------------------------------------------------
__global__ __launch_bounds__(256) void proj_kernel(const float* __restrict__ query,
                                                   const float* __restrict__ key,
                                                   const float* __restrict__ W1,
                                                   const float* __restrict__ b1){
    __shared__ float As[16][68];  // transposed [k][m], padded
    __shared__ float Ws[16][64];
    int tid = threadIdx.x;
    int colTile = blockIdx.x * 64;
    int rowTile = blockIdx.y * 64;
    bool isQ = rowTile < Bb*Qn;
    const float* A = isQ ? (query + (size_t)rowTile*Dd)
                         : (key + (size_t)(rowTile - Bb*Qn)*Dd);
    const float* W = W1 + (size_t)(isQ ? 0 : Dd)*Hh + colTile;

    int tx = tid & 15, ty = tid >> 4;
    int arow = tid >> 2;          // 0..63
    int ac4  = (tid & 3) * 4;     // 0,4,8,12
    int wrow = tid >> 4;          // 0..15
    int wc4  = (tid & 15) * 4;    // 0..60

    float acc[4][4];
    #pragma unroll
    for (int i = 0; i < 4; i++)
        #pragma unroll
        for (int j = 0; j < 4; j++) acc[i][j] = 0.0f;

    for (int k0 = 0; k0 < Dd; k0 += 16){
        float4 av = *(const float4*)(A + (size_t)arow*Dd + k0 + ac4);
        float4 wv = *(const float4*)(W + (size_t)(k0 + wrow)*Hh + wc4);
        __syncthreads();
        As[ac4+0][arow] = av.x; As[ac4+1][arow] = av.y;
        As[ac4+2][arow] = av.z; As[ac4+3][arow] = av.w;
        *(float4*)&Ws[wrow][wc4] = wv;
        __syncthreads();
        #pragma unroll
        for (int kk = 0; kk < 16; kk++){
            float4 a = *(const float4*)&As[kk][ty*4];
            float4 b = *(const float4*)&Ws[kk][tx*4];
            float ar[4] = {a.x, a.y, a.z, a.w};
            float br[4] = {b.x, b.y, b.z, b.w};
            #pragma unroll
            for (int i = 0; i < 4; i++)
                #pragma unroll
                for (int j = 0; j < 4; j++)
                    acc[i][j] += ar[i]*br[j];
        }
    }

    if (isQ){
        float* outp = g_qproj + (size_t)rowTile*Hh + colTile;
        #pragma unroll
        for (int i = 0; i < 4; i++)
            #pragma unroll
            for (int j = 0; j < 4; j++)
                outp[(size_t)(ty*4+i)*Hh + tx*4+j] = acc[i][j];
    } else {
        float* outp = g_kproj + (size_t)(rowTile - Bb*Qn)*Hh + colTile;
        #pragma unroll
        for (int i = 0; i < 4; i++)
            #pragma unroll
            for (int j = 0; j < 4; j++)
                outp[(size_t)(ty*4+i)*Hh + tx*4+j] = acc[i][j] + b1[colTile + tx*4+j];
    }
}

// ---------------------------------------------------------------------------
// Kernel 2: scores[b,q,k] = sum_h w2[h]*tanh(qp[b,q,h]+kp[b,k,h]).
// Block tile 32q x 64k, 256 threads, micro-tile 2q x 4k. MUFU-bound (near
// the chip tanh floor ~31us); mask + 1/sqrt(512) in epilogue.
// ---------------------------------------------------------------------------
__global__ __launch_bounds__(256) void score_kernel(const int* __restrict__ mask,
                                                    const float* __restrict__ w2){
    __shared__ float qs[32][36];  // [h][q]
    __shared__ float ks[32][68];  // [h][k]
    __shared__ float ws[32];
    int b  = blockIdx.z;
    int q0 = blockIdx.y * 32;
    int k0 = blockIdx.x * 64;
    int tid = threadIdx.x;
    int tx = tid & 15;    // k dim, TK=4
    int ty = tid >> 4;    // q dim, TQ=2
    const float* qbase = g_qproj + (size_t)(b*Qn + q0)*Hh;
    const float* kbase = g_kproj + (size_t)(b*Kn + k0)*Hh;

    float acc[2][4];
    #pragma unroll
    for (int i = 0; i < 2; i++)
        #pragma unroll
        for (int j = 0; j < 4; j++) acc[i][j] = 0.0f;

    int ql_r = tid >> 3;        // 0..31
    int ql_c = (tid & 7) * 4;   // 0..28
    int kl_r = tid >> 2;        // 0..63
    int kl_c = (tid & 3) * 4;   // 0..12

    for (int h0 = 0; h0 < Hh; h0 += 32){
        float4 qv4  = *(const float4*)(qbase + (size_t)ql_r*Hh + h0 + ql_c);
        float4 kv4a = *(const float4*)(kbase + (size_t)kl_r*Hh + h0 + kl_c);
        float4 kv4b = *(const float4*)(kbase + (size_t)kl_r*Hh + h0 + kl_c + 16);
        __syncthreads();
        qs[ql_c+0][ql_r] = qv4.x; qs[ql_c+1][ql_r] = qv4.y;
        qs[ql_c+2][ql_r] = qv4.z; qs[ql_c+3][ql_r] = qv4.w;
        ks[kl_c+0][kl_r] = kv4a.x; ks[kl_c+1][kl_r] = kv4a.y;
        ks[kl_c+2][kl_r] = kv4a.z; ks[kl_c+3][kl_r] = kv4a.w;
        ks[kl_c+16][kl_r] = kv4b.x; ks[kl_c+17][kl_r] = kv4b.y;
        ks[kl_c+18][kl_r] = kv4b.z; ks[kl_c+19][kl_r] = kv4b.w;
        if (tid < 32) ws[tid] = w2[h0 + tid];
        __syncthreads();
        #pragma unroll
        for (int h = 0; h < 32; h++){
            float wv = ws[h];
            float2 qv = *(const float2*)&qs[h][ty*2];
            float4 kv = *(const float4*)&ks[h][tx*4];
            float kr[4] = {kv.x, kv.y, kv.z, kv.w};
            #pragma unroll
            for (int j = 0; j < 4; j++){
                acc[0][j] += wv * fast_tanh(qv.x + kr[j]);
                acc[1][j] += wv * fast_tanh(qv.y + kr[j]);
            }
        }
    }

    const float rs = 0.04419417382415922f;  // 1/sqrt(512)
    #pragma unroll
    for (int j = 0; j < 4; j++){
        int kk = k0 + tx*4 + j;
        int m = mask[b*Kn + kk];
        #pragma unroll
        for (int i = 0; i < 2; i++){
            int qq = q0 + ty*2 + i;
            float s = (m != 0) ? -HUGEF : acc[i][j];
            g_scores[(size_t)(b*Qn + qq)*Kn + kk] = s * rs;
        }
    }
}

// ---------------------------------------------------------------------------
// Kernel 3: row softmax over K=256; writes attn_weights into d_out.
// ---------------------------------------------------------------------------
__global__ __launch_bounds__(256) void softmax_kernel(float* __restrict__ out_w){
    int row = blockIdx.x;     // 0..B*Q-1
    int t = threadIdx.x;      // 0..255
    int lane = t & 31, warp = t >> 5;
    __shared__ float red[8];
    float s = g_scores[(size_t)row*Kn + t];

    float m = s;
    #pragma unroll
    for (int o = 16; o > 0; o >>= 1) m = fmaxf(m, __shfl_xor_sync(0xffffffffu, m, o));
    if (lane == 0) red[warp] = m;
    __syncthreads();
    float m8 = red[0];
    #pragma unroll
    for (int i = 1; i < 8; i++) m8 = fmaxf(m8, red[i]);

    float e = __expf(s - m8);
    float sum = e;
    #pragma unroll
    for (int o = 16; o > 0; o >>= 1) sum += __shfl_xor_sync(0xffffffffu, sum, o);
    __syncthreads();
    if (lane == 0) red[warp] = sum;
    __syncthreads();
    float s8 = 0.0f;
    #pragma unroll
    for (int i = 0; i < 8; i++) s8 += red[i];

    out_w[(size_t)row*Kn + t] = e / s8;
}

// ---------------------------------------------------------------------------
// Kernel 4 (REWRITTEN): attn_vec = attn_w[b] (128x256) @ value[b] (256x512).
// Per-batch tiled GEMM: 64x64 tile, 256 threads, 4x4 micro-tile, k-chunk 16.
// Grid (8,2,8)=128 blocks = one wave. FMA-bound, ~10us target (was 45us
// latency-bound: occ 20.6%, issue 13.3%, serial load->FMA chain).
// ---------------------------------------------------------------------------
__global__ __launch_bounds__(256) void attnvec_kernel(const float* __restrict__ value,
                                                      const float* __restrict__ attn_w,
                                                      float* __restrict__ out_v){
    __shared__ float ws[16][68];  // [k][q] transposed, padded
    __shared__ float vs[16][68];  // [k][v]
    int b  = blockIdx.z;
    int q0 = blockIdx.y * 64;
    int v0 = blockIdx.x * 64;
    int tid = threadIdx.x;
    int tx = tid & 15, ty = tid >> 4;

    const float* wbase = attn_w + (size_t)(b*Qn + q0)*Kn;
    const float* vbase = value + (size_t)b*Kn*Vv + v0;

    // loader indices
    int wq = tid >> 2;            // 0..63  (q row)
    int wk4 = (tid & 3) * 4;      // 0,4,8,12 (k within chunk)
    int vk = tid >> 4;            // 0..15  (k row)
    int vc4 = (tid & 15) * 4;     // 0..60  (v col)

    float acc[4][4];
    #pragma unroll
    for (int i = 0; i < 4; i++)
        #pragma unroll
        for (int j = 0; j < 4; j++) acc[i][j] = 0.0f;

    for (int k0 = 0; k0 < Kn; k0 += 16){
        float4 wv = *(const float4*)(wbase + (size_t)wq*Kn + k0 + wk4);
        float4 vv = *(const float4*)(vbase + (size_t)(k0 + vk)*Vv + vc4);
        __syncthreads();
        ws[wk4+0][wq] = wv.x; ws[wk4+1][wq] = wv.y;
        ws[wk4+2][wq] = wv.z; ws[wk4+3][wq] = wv.w;
        *(float4*)&vs[vk][vc4] = vv;
        __syncthreads();
        #pragma unroll
        for (int kk = 0; kk < 16; kk++){
            float4 a = *(const float4*)&ws[kk][ty*4];
            float4 c = *(const float4*)&vs[kk][tx*4];
            float ar[4] = {a.x, a.y, a.z, a.w};
            float cr[4] = {c.x, c.y, c.z, c.w};
            #pragma unroll
            for (int i = 0; i < 4; i++)
                #pragma unroll
                for (int j = 0; j < 4; j++)
                    acc[i][j] += ar[i]*cr[j];
        }
    }

    float* outp = out_v + (size_t)(b*Qn + q0)*Vv + v0;
    #pragma unroll
    for (int i = 0; i < 4; i++){
        float4 o = make_float4(acc[i][0], acc[i][1], acc[i][2], acc[i][3]);
        *(float4*)(outp + (size_t)(ty*4+i)*Vv + tx*4) = o;
    }
}

// ---------------------------------------------------------------------------
extern "C" void kernel_launch(void* const* d_in, const int* in_sizes, int n_in,
                              void* d_out, int out_size){
    const float* query = (const float*)d_in[0];
    const float* key_  = (const float*)d_in[1];
    const float* value = (const float*)d_in[2];
    const int*   mask  = (const int*)  d_in[3];
    const float* W1    = (const float*)d_in[4];
    const float* b1    = (const float*)d_in[5];
    const float* w2    = (const float*)d_in[6];

    float* out = (float*)d_out;
    float* out_vec = out;                       // (B,Q,V)
    float* out_w   = out + (size_t)Bb*Qn*Vv;    // (B,Q,K)

    dim3 g1(Hh/64, (Bb*Qn + Bb*Kn)/64);         // (8, 48)
    proj_kernel<<<g1, 256>>>(query, key_, W1, b1);

    dim3 g2(Kn/64, Qn/32, Bb);                  // (4, 4, 8)
    score_kernel<<<g2, 256>>>(mask, w2);

    softmax_kernel<<<Bb*Qn, 256>>>(out_w);

    dim3 g4(Vv/64, Qn/64, Bb);                  // (8, 2, 8)
    attnvec_kernel<<<g4, 256>>>(value, out_w, out_vec);
}

// round 5
// speedup vs baseline: 1.0580x; 1.0580x over previous
#include <cuda_runtime.h>
#include <math.h>

#define Bb 8
#define Qn 128
#define Kn 256
#define Dd 512
#define Hh 512
#define Vv 512
#define HUGEF 1000000000.0f
#define RSQRT 0.04419417382415922f   // 1/sqrt(512)

// Scratch (allocation-free rule: __device__ globals)
__device__ float g_qproj[Bb*Qn*Hh];   // 2 MB
__device__ float g_kproj[Bb*Kn*Hh];   // 4 MB (compacted rows, b1 folded in)
__device__ float g_scores[Bb*Qn*Kn];  // 1 MB
__device__ int   g_kidx[Bb*Kn];       // compacted unmasked k indices (padded)
__device__ int   g_kcnt[Bb];          // unmasked count per batch

typedef unsigned long long u64;
__device__ __forceinline__ u64 pack2(float x, float y){
    u64 r; asm("mov.b64 %0, {%1,%2};" : "=l"(r) : "f"(x), "f"(y)); return r;
}
__device__ __forceinline__ void fma2(u64& d, u64 a, u64 b){
    asm("fma.rn.f32x2 %0, %1, %2, %0;" : "+l"(d) : "l"(a), "l"(b));
}
__device__ __forceinline__ void unpack2(u64 v, float& lo, float& hi){
    asm("mov.b64 {%0,%1}, %2;" : "=f"(lo), "=f"(hi) : "l"(v));
}
__device__ __forceinline__ float fast_tanh(float x){
    float r; asm("tanh.approx.f32 %0, %1;" : "=f"(r) : "f"(x)); return r;
}

// ---------------------------------------------------------------------------
// Kernel 0: per-batch compaction of unmasked k + prefill masked scores.
// ---------------------------------------------------------------------------
__global__ __launch_bounds__(256) void compact_kernel(const int* __restrict__ mask){
    int b = blockIdx.x, t = threadIdx.x;
    int lane = t & 31, w = t >> 5;
    int keep = (mask[b*Kn + t] == 0);
    unsigned bal = __ballot_sync(0xffffffffu, keep);
    int rank = __popc(bal & ((1u << lane) - 1u));
    __shared__ int wcnt[8];
    if (lane == 0) wcnt[w] = __popc(bal);
    __syncthreads();
    int off = 0, total = 0;
    #pragma unroll
    for (int i = 0; i < 8; i++){ if (i < w) off += wcnt[i]; total += wcnt[i]; }
    if (keep) g_kidx[b*Kn + off + rank] = t;
    // prefill masked score columns: exp underflows to exactly 0 in softmax
    if (!keep){
        float v = -HUGEF * RSQRT;
        for (int q = 0; q < Qn; q++)
            g_scores[(size_t)(b*Qn + q)*Kn + t] = v;
    }
    __syncthreads();   // g_kidx[b*Kn] visible within block
    int cntp = (total + 63) & ~63;
    int first = (total > 0) ? g_kidx[b*Kn] : 0;
    for (int i = total + t; i < cntp; i += 256) g_kidx[b*Kn + i] = first;
    if (t == 0) g_kcnt[b] = total;
}

// ---------------------------------------------------------------------------
// Kernel 1: projections with f32x2 FMA + single-sync double buffering.
// Tiles 0..15: query rows. Tiles 16..47: compacted key rows (gathered),
// blocks beyond padded count exit.
// ---------------------------------------------------------------------------
__global__ __launch_bounds__(256) void proj_kernel(const float* __restrict__ query,
                                                   const float* __restrict__ key,
                                                   const float* __restrict__ W1,
                                                   const float* __restrict__ b1){
    __shared__ float As[2][16][68];  // [buf][k][row]
    __shared__ float Ws[2][16][68];  // [buf][k][col]
    int tid = threadIdx.x;
    int colTile = blockIdx.x * 64;
    int tile = blockIdx.y;
    bool isQ = tile < (Bb*Qn/64);    // 16 q-tiles
    int arow = tid >> 2;             // 0..63
    int ac4  = (tid & 3) * 4;
    int b = 0, pos0 = 0;
    const float* Arow;
    if (isQ){
        Arow = query + (size_t)(tile*64 + arow)*Dd;
    } else {
        int t = tile - (Bb*Qn/64);   // 0..31
        b = t >> 2; pos0 = (t & 3) * 64;
        int cnt = g_kcnt[b];
        int cntp = (cnt + 63) & ~63;
        if (pos0 >= cntp) return;
        int kid = g_kidx[b*Kn + pos0 + arow];
        Arow = key + ((size_t)b*Kn + kid)*Dd;
    }
    const float* W = W1 + (size_t)(isQ ? 0 : Dd)*Hh + colTile;
    int tx = tid & 15, ty = tid >> 4;
    int wrow = tid >> 4, wc4 = (tid & 15) * 4;

    u64 acc2[4][2];
    #pragma unroll
    for (int i = 0; i < 4; i++){ acc2[i][0] = 0ull; acc2[i][1] = 0ull; }

    // prefetch chunk 0
    float4 av = *(const float4*)(Arow + ac4);
    float4 wv = *(const float4*)(W + (size_t)wrow*Hh + wc4);

    const int NCH = Dd/16;
    for (int ch = 0; ch < NCH; ch++){
        int cur = ch & 1;
        As[cur][ac4+0][arow] = av.x; As[cur][ac4+1][arow] = av.y;
        As[cur][ac4+2][arow] = av.z; As[cur][ac4+3][arow] = av.w;
        *(float4*)&Ws[cur][wrow][wc4] = wv;
        __syncthreads();
        if (ch + 1 < NCH){
            int k0 = (ch + 1) * 16;
            av = *(const float4*)(Arow + k0 + ac4);
            wv = *(const float4*)(W + (size_t)(k0 + wrow)*Hh + wc4);
        }
        #pragma unroll
        for (int kk = 0; kk < 16; kk++){
            float4 a = *(const float4*)&As[cur][kk][ty*4];
            ulonglong2 bv = *(const ulonglong2*)&Ws[cur][kk][tx*4];
            u64 ad;
            ad = pack2(a.x,a.x); fma2(acc2[0][0],ad,bv.x); fma2(acc2[0][1],ad,bv.y);
            ad = pack2(a.y,a.y); fma2(acc2[1][0],ad,bv.x); fma2(acc2[1][1],ad,bv.y);
            ad = pack2(a.z,a.z); fma2(acc2[2][0],ad,bv.x); fma2(acc2[2][1],ad,bv.y);
            ad = pack2(a.w,a.w); fma2(acc2[3][0],ad,bv.x); fma2(acc2[3][1],ad,bv.y);
        }
    }

    if (isQ){
        float* outp = g_qproj + (size_t)(tile*64)*Hh + colTile;
        #pragma unroll
        for (int i = 0; i < 4; i++){
            float o0,o1,o2,o3;
            unpack2(acc2[i][0],o0,o1); unpack2(acc2[i][1],o2,o3);
            *(float4*)(outp + (size_t)(ty*4+i)*Hh + tx*4) = make_float4(o0,o1,o2,o3);
        }
    } else {
        float* outp = g_kproj + ((size_t)b*Kn + pos0)*Hh + colTile;
        float4 bb = *(const float4*)(b1 + colTile + tx*4);
        #pragma unroll
        for (int i = 0; i < 4; i++){
            float o0,o1,o2,o3;
            unpack2(acc2[i][0],o0,o1); unpack2(acc2[i][1],o2,o3);
            *(float4*)(outp + (size_t)(ty*4+i)*Hh + tx*4) =
                make_float4(o0+bb.x, o1+bb.y, o2+bb.z, o3+bb.w);
        }
    }
}

// ---------------------------------------------------------------------------
// Kernel 2: scores over COMPACTED k only (~50% of the tanh work skipped).
// kproj is compacted-contiguous; epilogue scatters via sidx. MUFU-bound.
// ---------------------------------------------------------------------------
__global__ __launch_bounds__(256) void score_kernel(const float* __restrict__ w2){
    int b  = blockIdx.z;
    int cnt = g_kcnt[b];
    int cntp = (cnt + 63) & ~63;
    int k0 = blockIdx.x * 64;
    if (k0 >= cntp) return;
    __shared__ float qs[32][36];  // [h][q]
    __shared__ float ks[32][68];  // [h][k]
    __shared__ float wsm[32];
    __shared__ int sidx[64];
    int q0 = blockIdx.y * 32;
    int tid = threadIdx.x;
    if (tid < 64) sidx[tid] = g_kidx[b*Kn + k0 + tid];
    int tx = tid & 15;    // k dim, TK=4
    int ty = tid >> 4;    // q dim, TQ=2
    const float* qbase = g_qproj + (size_t)(b*Qn + q0)*Hh;
    const float* kbase = g_kproj + ((size_t)b*Kn + k0)*Hh;

    float acc[2][4];
    #pragma unroll
    for (int i = 0; i < 2; i++)
        #pragma unroll
        for (int j = 0; j < 4; j++) acc[i][j] = 0.0f;

    int ql_r = tid >> 3;        // 0..31
    int ql_c = (tid & 7) * 4;   // 0..28
    int kl_r = tid >> 2;        // 0..63
    int kl_c = (tid & 3) * 4;   // 0..12

    for (int h0 = 0; h0 < Hh; h0 += 32){
        float4 qv4  = *(const float4*)(qbase + (size_t)ql_r*Hh + h0 + ql_c);
        float4 kv4a = *(const float4*)(kbase + (size_t)kl_r*Hh + h0 + kl_c);
        float4 kv4b = *(const float4*)(kbase + (size_t)kl_r*Hh + h0 + kl_c + 16);
        __syncthreads();
        qs[ql_c+0][ql_r] = qv4.x; qs[ql_c+1][ql_r] = qv4.y;
        qs[ql_c+2][ql_r] = qv4.z; qs[ql_c+3][ql_r] = qv4.w;
        ks[kl_c+0][kl_r] = kv4a.x; ks[kl_c+1][kl_r] = kv4a.y;
        ks[kl_c+2][kl_r] = kv4a.z; ks[kl_c+3][kl_r] = kv4a.w;
        ks[kl_c+16][kl_r] = kv4b.x; ks[kl_c+17][kl_r] = kv4b.y;
        ks[kl_c+18][kl_r] = kv4b.z; ks[kl_c+19][kl_r] = kv4b.w;
        if (tid < 32) wsm[tid] = w2[h0 + tid];
        __syncthreads();
        #pragma unroll
        for (int h = 0; h < 32; h++){
            float wv = wsm[h];
            float2 qv = *(const float2*)&qs[h][ty*2];
            float4 kv = *(const float4*)&ks[h][tx*4];
            float kr[4] = {kv.x, kv.y, kv.z, kv.w};
            #pragma unroll
            for (int j = 0; j < 4; j++){
                acc[0][j] += wv * fast_tanh(qv.x + kr[j]);
                acc[1][j] += wv * fast_tanh(qv.y + kr[j]);
            }
        }
    }

    #pragma unroll
    for (int j = 0; j < 4; j++){
        int realk = sidx[tx*4 + j];
        #pragma unroll
        for (int i = 0; i < 2; i++){
            int qq = q0 + ty*2 + i;
            g_scores[(size_t)(b*Qn + qq)*Kn + realk] = acc[i][j] * RSQRT;
        }
    }
}

// ---------------------------------------------------------------------------
// Kernel 3: row softmax over K=256; masked columns hold -HUGE*rs -> exp = 0.
// ---------------------------------------------------------------------------
__global__ __launch_bounds__(256) void softmax_kernel(float* __restrict__ out_w){
    int row = blockIdx.x;
    int t = threadIdx.x;
    int lane = t & 31, warp = t >> 5;
    __shared__ float red[8];
    float s = g_scores[(size_t)row*Kn + t];

    float m = s;
    #pragma unroll
    for (int o = 16; o > 0; o >>= 1) m = fmaxf(m, __shfl_xor_sync(0xffffffffu, m, o));
    if (lane == 0) red[warp] = m;
    __syncthreads();
    float m8 = red[0];
    #pragma unroll
    for (int i = 1; i < 8; i++) m8 = fmaxf(m8, red[i]);

    float e = __expf(s - m8);
    float sum = e;
    #pragma unroll
    for (int o = 16; o > 0; o >>= 1) sum += __shfl_xor_sync(0xffffffffu, sum, o);
    __syncthreads();
    if (lane == 0) red[warp] = sum;
    __syncthreads();
    float s8 = 0.0f;
    #pragma unroll
    for (int i = 0; i < 8; i++) s8 += red[i];

    out_w[(size_t)row*Kn + t] = e / s8;
}

// ---------------------------------------------------------------------------
// Kernel 4: attn_vec GEMM over compacted k (masked weights are exactly 0),
// f32x2 FMA + single-sync double buffering. cnt==0 falls back to identity.
// ---------------------------------------------------------------------------
__global__ __launch_bounds__(256) void attnvec_kernel(const float* __restrict__ value,
                                                      const float* __restrict__ attn_w,
                                                      float* __restrict__ out_v){
    __shared__ float ws[2][16][68];
    __shared__ float vs[2][16][68];
    __shared__ int sidx[Kn];
    int b  = blockIdx.z;
    int q0 = blockIdx.y * 64;
    int v0 = blockIdx.x * 64;
    int tid = threadIdx.x;
    int tx = tid & 15, ty = tid >> 4;
    int cnt = g_kcnt[b];
    bool useidx = (cnt > 0);
    int n  = useidx ? cnt : Kn;
    int np = (n + 15) & ~15;
    for (int i = tid; i < np; i += 256) sidx[i] = useidx ? g_kidx[b*Kn + i] : i;
    __syncthreads();

    int wq = tid >> 2, wk4 = (tid & 3) * 4;
    int vk = tid >> 4, vc4 = (tid & 15) * 4;
    const float* wrow  = attn_w + (size_t)(b*Qn + q0 + wq)*Kn;
    const float* vbase = value + (size_t)b*Kn*Vv + v0 + vc4;

    u64 acc2[4][2];
    #pragma unroll
    for (int i = 0; i < 4; i++){ acc2[i][0] = 0ull; acc2[i][1] = 0ull; }

    // prefetch chunk 0
    float wr[4]; float4 vv;
    #pragma unroll
    for (int i = 0; i < 4; i++){
        int pos = wk4 + i;
        wr[i] = (pos < n) ? wrow[sidx[pos]] : 0.0f;
    }
    vv = *(const float4*)(vbase + (size_t)sidx[vk]*Vv);

    int nch = np / 16;
    for (int ch = 0; ch < nch; ch++){
        int cur = ch & 1;
        ws[cur][wk4+0][wq] = wr[0]; ws[cur][wk4+1][wq] = wr[1];
        ws[cur][wk4+2][wq] = wr[2]; ws[cur][wk4+3][wq] = wr[3];
        *(float4*)&vs[cur][vk][vc4] = vv;
        __syncthreads();
        if (ch + 1 < nch){
            int k0 = (ch + 1) * 16;
            #pragma unroll
            for (int i = 0; i < 4; i++){
                int pos = k0 + wk4 + i;
                wr[i] = (pos < n) ? wrow[sidx[pos]] : 0.0f;
            }
            vv = *(const float4*)(vbase + (size_t)sidx[k0 + vk]*Vv);
        }
        #pragma unroll
        for (int kk = 0; kk < 16; kk++){
            float4 a = *(const float4*)&ws[cur][kk][ty*4];
            ulonglong2 cv = *(const ulonglong2*)&vs[cur][kk][tx*4];
            u64 ad;
            ad = pack2(a.x,a.x); fma2(acc2[0][0],ad,cv.x); fma2(acc2[0][1],ad,cv.y);
            ad = pack2(a.y,a.y); fma2(acc2[1][0],ad,cv.x); fma2(acc2[1][1],ad,cv.y);
            ad = pack2(a.z,a.z); fma2(acc2[2][0],ad,cv.x); fma2(acc2[2][1],ad,cv.y);
            ad = pack2(a.w,a.w); fma2(acc2[3][0],ad,cv.x); fma2(acc2[3][1],ad,cv.y);
        }
    }

    float* outp = out_v + (size_t)(b*Qn + q0)*Vv + v0;
    #pragma unroll
    for (int i = 0; i < 4; i++){
        float o0,o1,o2,o3;
        unpack2(acc2[i][0],o0,o1); unpack2(acc2[i][1],o2,o3);
        *(float4*)(outp + (size_t)(ty*4+i)*Vv + tx*4) = make_float4(o0,o1,o2,o3);
    }
}

// ---------------------------------------------------------------------------
extern "C" void kernel_launch(void* const* d_in, const int* in_sizes, int n_in,
                              void* d_out, int out_size){
    const float* query = (const float*)d_in[0];
    const float* key_  = (const float*)d_in[1];
    const float* value = (const float*)d_in[2];
    const int*   mask  = (const int*)  d_in[3];
    const float* W1    = (const float*)d_in[4];
    const float* b1    = (const float*)d_in[5];
    const float* w2    = (const float*)d_in[6];

    float* out = (float*)d_out;
    float* out_vec = out;                       // (B,Q,V)
    float* out_w   = out + (size_t)Bb*Qn*Vv;    // (B,Q,K)

    compact_kernel<<<Bb, 256>>>(mask);

    dim3 g1(Hh/64, (Bb*Qn + Bb*Kn)/64);         // (8, 48); key tiles may exit
    proj_kernel<<<g1, 256>>>(query, key_, W1, b1);

    dim3 g2(Kn/64, Qn/32, Bb);                  // (4, 4, 8); ~half exit
    score_kernel<<<g2, 256>>>(w2);

    softmax_kernel<<<Bb*Qn, 256>>>(out_w);

    dim3 g4(Vv/64, Qn/64, Bb);                  // (8, 2, 8)
    attnvec_kernel<<<g4, 256>>>(value, out_w, out_vec);
}

// round 7
// speedup vs baseline: 1.1570x; 1.0936x over previous
#include <cuda_runtime.h>
#include <math.h>

#define Bb 8
#define Qn 128
#define Kn 256
#define Dd 512
#define Hh 512
#define Vv 512
#define HUGEF 1000000000.0f
#define RSQRT 0.04419417382415922f   // 1/sqrt(512)

// Scratch (allocation-free rule: __device__ globals)
__device__ float g_qproj[Bb*Qn*Hh];   // 2 MB
__device__ float g_kproj[Bb*Kn*Hh];   // 4 MB (compacted rows, b1 folded in)
__device__ float g_scores[Bb*Qn*Kn];  // 1 MB (only unmasked cols written)
__device__ int   g_kidx[Bb*Kn];       // compacted unmasked k indices (padded)
__device__ int   g_kcnt[Bb];          // unmasked count per batch

typedef unsigned long long u64;
__device__ __forceinline__ u64 pack2(float x, float y){
    u64 r; asm("mov.b64 %0, {%1,%2};" : "=l"(r) : "f"(x), "f"(y)); return r;
}
__device__ __forceinline__ void fma2(u64& d, u64 a, u64 b){
    asm("fma.rn.f32x2 %0, %1, %2, %0;" : "+l"(d) : "l"(a), "l"(b));
}
__device__ __forceinline__ void unpack2(u64 v, float& lo, float& hi){
    asm("mov.b64 {%0,%1}, %2;" : "=f"(lo), "=f"(hi) : "l"(v));
}
__device__ __forceinline__ float fast_tanh(float x){
    float r; asm("tanh.approx.f32 %0, %1;" : "=f"(r) : "f"(x)); return r;
}

// ---------------------------------------------------------------------------
// Kernel 0: per-batch compaction of unmasked k (64-padded with first index).
// ---------------------------------------------------------------------------
__global__ __launch_bounds__(256) void compact_kernel(const int* __restrict__ mask){
    int b = blockIdx.x, t = threadIdx.x;
    int lane = t & 31, w = t >> 5;
    int keep = (mask[b*Kn + t] == 0);
    unsigned bal = __ballot_sync(0xffffffffu, keep);
    int rank = __popc(bal & ((1u << lane) - 1u));
    __shared__ int wcnt[8];
    if (lane == 0) wcnt[w] = __popc(bal);
    __syncthreads();
    int off = 0, total = 0;
    #pragma unroll
    for (int i = 0; i < 8; i++){ if (i < w) off += wcnt[i]; total += wcnt[i]; }
    if (keep) g_kidx[b*Kn + off + rank] = t;
    __syncthreads();
    int cntp = (total + 63) & ~63;
    int first = (total > 0) ? g_kidx[b*Kn] : 0;
    for (int i = total + t; i < cntp; i += 256) g_kidx[b*Kn + i] = first;
    if (t == 0) g_kcnt[b] = total;
}

// ---------------------------------------------------------------------------
// Kernel 1: projections, f32x2 FMA, single-sync double buffering.
// Tiles 0..15: query rows; tiles 16..47: compacted key rows (b1 folded).
// ---------------------------------------------------------------------------
__global__ __launch_bounds__(256) void proj_kernel(const float* __restrict__ query,
                                                   const float* __restrict__ key,
                                                   const float* __restrict__ W1,
                                                   const float* __restrict__ b1){
    __shared__ float As[2][16][68];
    __shared__ float Ws[2][16][68];
    int tid = threadIdx.x;
    int colTile = blockIdx.x * 64;
    int tile = blockIdx.y;
    bool isQ = tile < (Bb*Qn/64);
    int arow = tid >> 2;
    int ac4  = (tid & 3) * 4;
    int b = 0, pos0 = 0;
    const float* Arow;
    if (isQ){
        Arow = query + (size_t)(tile*64 + arow)*Dd;
    } else {
        int t = tile - (Bb*Qn/64);
        b = t >> 2; pos0 = (t & 3) * 64;
        int cnt = g_kcnt[b];
        int cntp = (cnt + 63) & ~63;
        if (pos0 >= cntp) return;
        int kid = g_kidx[b*Kn + pos0 + arow];
        Arow = key + ((size_t)b*Kn + kid)*Dd;
    }
    const float* W = W1 + (size_t)(isQ ? 0 : Dd)*Hh + colTile;
    int tx = tid & 15, ty = tid >> 4;
    int wrow = tid >> 4, wc4 = (tid & 15) * 4;

    u64 acc2[4][2];
    #pragma unroll
    for (int i = 0; i < 4; i++){ acc2[i][0] = 0ull; acc2[i][1] = 0ull; }

    float4 av = *(const float4*)(Arow + ac4);
    float4 wv = *(const float4*)(W + (size_t)wrow*Hh + wc4);

    const int NCH = Dd/16;
    for (int ch = 0; ch < NCH; ch++){
        int cur = ch & 1;
        As[cur][ac4+0][arow] = av.x; As[cur][ac4+1][arow] = av.y;
        As[cur][ac4+2][arow] = av.z; As[cur][ac4+3][arow] = av.w;
        *(float4*)&Ws[cur][wrow][wc4] = wv;
        __syncthreads();
        if (ch + 1 < NCH){
            int k0 = (ch + 1) * 16;
            av = *(const float4*)(Arow + k0 + ac4);
            wv = *(const float4*)(W + (size_t)(k0 + wrow)*Hh + wc4);
        }
        #pragma unroll
        for (int kk = 0; kk < 16; kk++){
            float4 a = *(const float4*)&As[cur][kk][ty*4];
            ulonglong2 bv = *(const ulonglong2*)&Ws[cur][kk][tx*4];
            u64 ad;
            ad = pack2(a.x,a.x); fma2(acc2[0][0],ad,bv.x); fma2(acc2[0][1],ad,bv.y);
            ad = pack2(a.y,a.y); fma2(acc2[1][0],ad,bv.x); fma2(acc2[1][1],ad,bv.y);
            ad = pack2(a.z,a.z); fma2(acc2[2][0],ad,bv.x); fma2(acc2[2][1],ad,bv.y);
            ad = pack2(a.w,a.w); fma2(acc2[3][0],ad,bv.x); fma2(acc2[3][1],ad,bv.y);
        }
    }

    if (isQ){
        float* outp = g_qproj + (size_t)(tile*64)*Hh + colTile;
        #pragma unroll
        for (int i = 0; i < 4; i++){
            float o0,o1,o2,o3;
            unpack2(acc2[i][0],o0,o1); unpack2(acc2[i][1],o2,o3);
            *(float4*)(outp + (size_t)(ty*4+i)*Hh + tx*4) = make_float4(o0,o1,o2,o3);
        }
    } else {
        float* outp = g_kproj + ((size_t)b*Kn + pos0)*Hh + colTile;
        float4 bb = *(const float4*)(b1 + colTile + tx*4);
        #pragma unroll
        for (int i = 0; i < 4; i++){
            float o0,o1,o2,o3;
            unpack2(acc2[i][0],o0,o1); unpack2(acc2[i][1],o2,o3);
            *(float4*)(outp + (size_t)(ty*4+i)*Vv + tx*4) =
                make_float4(o0+bb.x, o1+bb.y, o2+bb.z, o3+bb.w);
        }
    }
}

// ---------------------------------------------------------------------------
// Kernel 2: scores over compacted k. SMALL tiles for chip-wide MUFU balance:
// 16q x 32k per block (micro 1q x 2k), grid up to 512 blocks (~256 active).
// Single-sync double-buffered. Chip floor ~16us.
// ---------------------------------------------------------------------------
__global__ __launch_bounds__(256) void score_kernel(const float* __restrict__ w2){
    int b  = blockIdx.z;
    int cnt = g_kcnt[b];
    int cntp = (cnt + 63) & ~63;
    int k0 = blockIdx.x * 32;
    if (k0 >= cntp) return;
    int q0 = blockIdx.y * 16;
    __shared__ float qs[2][32][17];   // [buf][h][q]
    __shared__ float ks[2][32][34];   // [buf][h][k] (stride 34 -> f32x2-aligned)
    __shared__ float wsm[2][32];
    __shared__ int sidx[32];
    int tid = threadIdx.x;
    if (tid < 32) sidx[tid] = g_kidx[b*Kn + k0 + tid];
    int tx = tid & 15;    // k pair
    int ty = tid >> 4;    // q (one per thread)
    const float* qbase = g_qproj + (size_t)(b*Qn + q0)*Hh;
    const float* kbase = g_kproj + ((size_t)b*Kn + k0)*Hh;

    float acc0 = 0.0f, acc1 = 0.0f;

    int qr = tid >> 3, qc4 = (tid & 7) * 4;   // tid<128 loads q tile
    int kr = tid >> 3, kc4 = (tid & 7) * 4;   // all 256 load k tile

    float4 qv4 = make_float4(0,0,0,0), kv4;
    float wv0 = 0.0f;
    if (tid < 128) qv4 = *(const float4*)(qbase + (size_t)qr*Hh + qc4);
    kv4 = *(const float4*)(kbase + (size_t)kr*Hh + kc4);
    if (tid < 32) wv0 = w2[tid];

    const int NCH = Hh/32;
    for (int ch = 0; ch < NCH; ch++){
        int cur = ch & 1;
        if (tid < 128){
            qs[cur][qc4+0][qr] = qv4.x; qs[cur][qc4+1][qr] = qv4.y;
            qs[cur][qc4+2][qr] = qv4.z; qs[cur][qc4+3][qr] = qv4.w;
        }
        ks[cur][kc4+0][kr] = kv4.x; ks[cur][kc4+1][kr] = kv4.y;
        ks[cur][kc4+2][kr] = kv4.z; ks[cur][kc4+3][kr] = kv4.w;
        if (tid < 32) wsm[cur][tid] = wv0;
        __syncthreads();
        if (ch + 1 < NCH){
            int h0 = (ch + 1) * 32;
            if (tid < 128) qv4 = *(const float4*)(qbase + (size_t)qr*Hh + h0 + qc4);
            kv4 = *(const float4*)(kbase + (size_t)kr*Hh + h0 + kc4);
            if (tid < 32) wv0 = w2[h0 + tid];
        }
        #pragma unroll
        for (int h = 0; h < 32; h++){
            float wv = wsm[cur][h];
            float qv = qs[cur][h][ty];
            float2 kv = *(const float2*)&ks[cur][h][tx*2];
            acc0 += wv * fast_tanh(qv + kv.x);
            acc1 += wv * fast_tanh(qv + kv.y);
        }
    }

    int qq = b*Qn + q0 + ty;
    g_scores[(size_t)qq*Kn + sidx[tx*2+0]] = acc0 * RSQRT;
    g_scores[(size_t)qq*Kn + sidx[tx*2+1]] = acc1 * RSQRT;
}

// ---------------------------------------------------------------------------
// Kernel 3: row softmax; masked cols substituted in-register (exp -> 0).
// ---------------------------------------------------------------------------
__global__ __launch_bounds__(256) void softmax_kernel(const int* __restrict__ mask,
                                                      float* __restrict__ out_w){
    int row = blockIdx.x;           // b*Qn + q
    int b = row >> 7;               // Qn = 128
    int t = threadIdx.x;
    int lane = t & 31, warp = t >> 5;
    __shared__ float red[8];
    float s = (mask[b*Kn + t] != 0) ? (-HUGEF * RSQRT)
                                    : g_scores[(size_t)row*Kn + t];

    float m = s;
    #pragma unroll
    for (int o = 16; o > 0; o >>= 1) m = fmaxf(m, __shfl_xor_sync(0xffffffffu, m, o));
    if (lane == 0) red[warp] = m;
    __syncthreads();
    float m8 = red[0];
    #pragma unroll
    for (int i = 1; i < 8; i++) m8 = fmaxf(m8, red[i]);

    float e = __expf(s - m8);
    float sum = e;
    #pragma unroll
    for (int o = 16; o > 0; o >>= 1) sum += __shfl_xor_sync(0xffffffffu, sum, o);
    __syncthreads();
    if (lane == 0) red[warp] = sum;
    __syncthreads();
    float s8 = 0.0f;
    #pragma unroll
    for (int i = 0; i < 8; i++) s8 += red[i];

    out_w[(size_t)row*Kn + t] = e / s8;
}

// ---------------------------------------------------------------------------
// Kernel 4: attn_vec GEMM over compacted k. 32q x 64v tiles (256 blocks),
// micro 2q x 4v, f32x2 FMA, single-sync double buffering.
// ---------------------------------------------------------------------------
__global__ __launch_bounds__(256) void attnvec_kernel(const float* __restrict__ value,
                                                      const float* __restrict__ attn_w,
                                                      float* __restrict__ out_v){
    __shared__ float ws[2][16][33];
    __shared__ float vs[2][16][68];
    __shared__ int sidx[Kn];
    int b  = blockIdx.z;
    int q0 = blockIdx.y * 32;
    int v0 = blockIdx.x * 64;
    int tid = threadIdx.x;
    int tx = tid & 15, ty = tid >> 4;
    int cnt = g_kcnt[b];
    bool useidx = (cnt > 0);
    int n  = useidx ? cnt : Kn;
    int np = (n + 15) & ~15;
    for (int i = tid; i < np; i += 256) sidx[i] = useidx ? g_kidx[b*Kn + i] : i;
    __syncthreads();

    int wq = tid >> 3, wk2 = (tid & 7) * 2;   // w tile: 32q x 16k, 2/thread
    int vk = tid >> 4, vc4 = (tid & 15) * 4;  // v tile: 16k x 64v, 4/thread
    const float* wrow  = attn_w + (size_t)(b*Qn + q0 + wq)*Kn;
    const float* vbase = value + (size_t)b*Kn*Vv + v0 + vc4;

    u64 acc2[2][2];
    acc2[0][0]=0ull; acc2[0][1]=0ull; acc2[1][0]=0ull; acc2[1][1]=0ull;

    float wr0, wr1; float4 vv;
    wr0 = (wk2+0 < n) ? wrow[sidx[wk2+0]] : 0.0f;
    wr1 = (wk2+1 < n) ? wrow[sidx[wk2+1]] : 0.0f;
    vv = *(const float4*)(vbase + (size_t)sidx[vk]*Vv);

    int nch = np / 16;
    for (int ch = 0; ch < nch; ch++){
        int cur = ch & 1;
        ws[cur][wk2+0][wq] = wr0;
        ws[cur][wk2+1][wq] = wr1;
        *(float4*)&vs[cur][vk][vc4] = vv;
        __syncthreads();
        if (ch + 1 < nch){
            int k0 = (ch + 1) * 16;
            wr0 = (k0+wk2+0 < n) ? wrow[sidx[k0+wk2+0]] : 0.0f;
            wr1 = (k0+wk2+1 < n) ? wrow[sidx[k0+wk2+1]] : 0.0f;
            vv = *(const float4*)(vbase + (size_t)sidx[k0+vk]*Vv);
        }
        #pragma unroll
        for (int kk = 0; kk < 16; kk++){
            float a0 = ws[cur][kk][ty*2+0];
            float a1 = ws[cur][kk][ty*2+1];
            ulonglong2 cv = *(const ulonglong2*)&vs[cur][kk][tx*4];
            u64 ad;
            ad = pack2(a0,a0); fma2(acc2[0][0],ad,cv.x); fma2(acc2[0][1],ad,cv.y);
            ad = pack2(a1,a1); fma2(acc2[1][0],ad,cv.x); fma2(acc2[1][1],ad,cv.y);
        }
    }

    float* outp = out_v + (size_t)(b*Qn + q0)*Vv + v0;
    #pragma unroll
    for (int i = 0; i < 2; i++){
        float o0,o1,o2,o3;
        unpack2(acc2[i][0],o0,o1); unpack2(acc2[i][1],o2,o3);
        *(float4*)(outp + (size_t)(ty*2+i)*Vv + tx*4) = make_float4(o0,o1,o2,o3);
    }
}

// ---------------------------------------------------------------------------
extern "C" void kernel_launch(void* const* d_in, const int* in_sizes, int n_in,
                              void* d_out, int out_size){
    const float* query = (const float*)d_in[0];
    const float* key_  = (const float*)d_in[1];
    const float* value = (const float*)d_in[2];
    const int*   mask  = (const int*)  d_in[3];
    const float* W1    = (const float*)d_in[4];
    const float* b1    = (const float*)d_in[5];
    const float* w2    = (const float*)d_in[6];

    float* out = (float*)d_out;
    float* out_vec = out;                       // (B,Q,V)
    float* out_w   = out + (size_t)Bb*Qn*Vv;    // (B,Q,K)

    compact_kernel<<<Bb, 256>>>(mask);

    dim3 g1(Hh/64, (Bb*Qn + Bb*Kn)/64);         // (8, 48); key tiles may exit
    proj_kernel<<<g1, 256>>>(query, key_, W1, b1);

    dim3 g2(Kn/32, Qn/16, Bb);                  // (8, 8, 8); ~half exit
    score_kernel<<<g2, 256>>>(w2);

    softmax_kernel<<<Bb*Qn, 256>>>(mask, out_w);

    dim3 g4(Vv/64, Qn/32, Bb);                  // (8, 4, 8)
    attnvec_kernel<<<g4, 256>>>(value, out_w, out_vec);
}